// round 7
// baseline (speedup 1.0000x reference)
#include <cuda_runtime.h>
#include <math.h>

// Diffusion: out = expm(-max(t,1e-8)*L) @ x, L = graph Laplacian (~32 nnz/row).
// Chebyshev expansion of e^{-t*lambda} on [0, 2*d_max] (Gershgorin), applied
// via fp32 sparse matvecs. EVERYTHING in one persistent kernel:
//   - per-block ELL extraction of its own 8 rows from dense L (smem-resident)
//   - atomic-free flag-array grid barrier (generation-persistent across graph
//     replays: each block reads its own flag as base; barrier count per launch
//     is deterministic and identical for all blocks)
//   - redundant per-block fp64 DCT for coefficients (identical -> safe)
//   - Chebyshev recurrence with out/T_{j-1} in registers, T_{j-2} in smem

#define NN   2048
#define DD   512
#define ELLW 128          // max off-diag nnz per row (mean ~32, max ~60)
#define MMAX 48
#define RPB  8            // rows per block
#define TPR  64           // threads per row (8 channels each)
#define THREADS (RPB*TPR) // 512
#define GRID (NN/RPB)     // 256 blocks (<= 148 SMs * 2 resident -> one wave)

// -------- device-global scratch (no allocations allowed) --------
__device__ float        g_T1[NN * DD];
__device__ float        g_T2[NN * DD];
__device__ volatile int g_arrive[GRID];    // flag barrier, monotone generations
__device__ float        g_blockmax[GRID];  // per-block max weighted degree

__device__ __forceinline__ float4 f4_load(const float* p) {
    return *reinterpret_cast<const float4*>(p);
}
__device__ __forceinline__ void f4_store(float* p, float4 v) {
    *reinterpret_cast<float4*>(p) = v;
}

// Atomic-free grid barrier: every block publishes its generation; threads
// 0..GRID-1 of every block poll all flags (coalesced). No shared counter.
__device__ __forceinline__ void flag_barrier(int bar_base, int& bar_num) {
    __syncthreads();
    __threadfence();
    bar_num++;
    const int target = bar_base + bar_num;
    if (threadIdx.x == 0) g_arrive[blockIdx.x] = target;
    if (threadIdx.x < GRID) {
        while (g_arrive[threadIdx.x] < target) { }
    }
    __threadfence();
    __syncthreads();
}

// ---------------------------------------------------------------------------
// SpMV core: acc[0..7] = d*yk - sum_j val_j * Y[col_j, ch..ch+7]
// ---------------------------------------------------------------------------
__device__ __forceinline__ void spmv8(const float* __restrict__ Y, int ch,
                                      const int* __restrict__ sc,
                                      const float* __restrict__ sv,
                                      int cnt, float d,
                                      const float yk[8], float acc[8]) {
#pragma unroll
    for (int i = 0; i < 8; i++) acc[i] = d * yk[i];
    int k = 0;
    for (; k + 2 <= cnt; k += 2) {
        int   c0 = sc[k],     c1 = sc[k + 1];
        float v0 = sv[k],     v1 = sv[k + 1];
        const float* p0 = Y + (((size_t)c0) << 9) + ch;
        const float* p1 = Y + (((size_t)c1) << 9) + ch;
        float4 a0 = f4_load(p0), a1 = f4_load(p0 + 4);
        float4 b0 = f4_load(p1), b1 = f4_load(p1 + 4);
        acc[0] -= v0 * a0.x; acc[1] -= v0 * a0.y; acc[2] -= v0 * a0.z; acc[3] -= v0 * a0.w;
        acc[4] -= v0 * a1.x; acc[5] -= v0 * a1.y; acc[6] -= v0 * a1.z; acc[7] -= v0 * a1.w;
        acc[0] -= v1 * b0.x; acc[1] -= v1 * b0.y; acc[2] -= v1 * b0.z; acc[3] -= v1 * b0.w;
        acc[4] -= v1 * b1.x; acc[5] -= v1 * b1.y; acc[6] -= v1 * b1.z; acc[7] -= v1 * b1.w;
    }
    if (k < cnt) {
        int   c0 = sc[k];
        float v0 = sv[k];
        const float* p0 = Y + (((size_t)c0) << 9) + ch;
        float4 a0 = f4_load(p0), a1 = f4_load(p0 + 4);
        acc[0] -= v0 * a0.x; acc[1] -= v0 * a0.y; acc[2] -= v0 * a0.z; acc[3] -= v0 * a0.w;
        acc[4] -= v0 * a1.x; acc[5] -= v0 * a1.y; acc[6] -= v0 * a1.z; acc[7] -= v0 * a1.w;
    }
}

// ---------------------------------------------------------------------------
__global__ void __launch_bounds__(THREADS, 2)
cheb_all(const float* __restrict__ X, const float* __restrict__ L,
         const float* __restrict__ t_in, float* __restrict__ out) {
    const int tid  = threadIdx.x;
    const int rl   = tid >> 6;          // row within block (0..7)
    const int lane = tid & 63;          // thread within row (2 full warps)
    const int row  = blockIdx.x * RPB + rl;

    __shared__ int    s_col[RPB][ELLW];
    __shared__ float  s_val[RPB][ELLW];
    __shared__ float  s_ykm1[RPB][TPR * 8];
    __shared__ float  s_diag[RPB];
    __shared__ int    s_cnt[RPB];
    __shared__ int    s_wt[RPB][2];
    __shared__ float  s_coef[MMAX + 1];
    __shared__ float  s_a;
    __shared__ int    s_deg;
    __shared__ double s_c[MMAX + 1];

    const int bar_base = g_arrive[blockIdx.x];   // persistent generation base
    int bar_num = 0;

    // ============ A) extract this block's 8 rows of dense L into smem ELL
    const float4* Lr4 = reinterpret_cast<const float4*>(L + (size_t)row * NN) + lane * 8;
    int   cnt = 0;
    float dv  = 0.f;
#pragma unroll
    for (int k = 0; k < 8; k++) {
        float4 v = Lr4[k];
        int c = lane * 32 + k * 4;
        if (c + 0 == row) dv = v.x; else cnt += (v.x != 0.f);
        if (c + 1 == row) dv = v.y; else cnt += (v.y != 0.f);
        if (c + 2 == row) dv = v.z; else cnt += (v.z != 0.f);
        if (c + 3 == row) dv = v.w; else cnt += (v.w != 0.f);
    }
    // 64-lane exclusive scan (warp scan + cross-warp combine)
    int inc = cnt;
#pragma unroll
    for (int off = 1; off < 32; off <<= 1) {
        int n = __shfl_up_sync(0xffffffffu, inc, off);
        if ((lane & 31) >= off) inc += n;
    }
    const int wir = lane >> 5;
    if ((lane & 31) == 31) s_wt[rl][wir] = inc;
    __syncthreads();
    int offset = inc - cnt + (wir ? s_wt[rl][0] : 0);
    int total  = s_wt[rl][0] + s_wt[rl][1];

    {   // pass 2: re-read (L1-hot) and compact into smem
        int o = offset;
#pragma unroll
        for (int k = 0; k < 8; k++) {
            float4 v = Lr4[k];
            int c = lane * 32 + k * 4;
            if (v.x != 0.f && c + 0 != row && o < ELLW) { s_col[rl][o] = c + 0; s_val[rl][o] = -v.x; o++; }
            if (v.y != 0.f && c + 1 != row && o < ELLW) { s_col[rl][o] = c + 1; s_val[rl][o] = -v.y; o++; }
            if (v.z != 0.f && c + 2 != row && o < ELLW) { s_col[rl][o] = c + 2; s_val[rl][o] = -v.z; o++; }
            if (v.w != 0.f && c + 3 != row && o < ELLW) { s_col[rl][o] = c + 3; s_val[rl][o] = -v.w; o++; }
        }
    }
    if (lane == (row >> 5)) s_diag[rl] = dv;    // owner of diagonal column
    if (lane == 0) s_cnt[rl] = (total < ELLW) ? total : ELLW;
    __syncthreads();

    if (tid == 0) {
        float m = s_diag[0];
#pragma unroll
        for (int i = 1; i < RPB; i++) m = fmaxf(m, s_diag[i]);
        g_blockmax[blockIdx.x] = m;
    }

    // issue own-row X loads early (overlap with barrier + DCT)
    const int   ch   = lane << 3;
    const size_t ridx = (((size_t)row) << 9) + ch;
    float yk[8];
    {
        float4 xa = f4_load(X + ridx), xb = f4_load(X + ridx + 4);
        yk[0] = xa.x; yk[1] = xa.y; yk[2] = xa.z; yk[3] = xa.w;
        yk[4] = xb.x; yk[5] = xb.y; yk[6] = xb.z; yk[7] = xb.w;
    }

    // ============ B) barrier: publish g_blockmax
    flag_barrier(bar_base, bar_num);

    // ============ C) coefficients (every block redundantly; warp 0)
    if (tid < 32) {
        float m = 0.f;
        for (int i = tid; i < GRID; i += 32) m = fmaxf(m, g_blockmax[i]);
#pragma unroll
        for (int off = 16; off; off >>= 1)
            m = fmaxf(m, __shfl_xor_sync(0xffffffffu, m, off));
        double lub = 2.0 * (double)m;               // Gershgorin
        if (lub < 1e-12) lub = 1e-12;

        double tt = (double)fmaxf(t_in[0], 1e-8f);
        double z  = 0.5 * tt * lub;

        const double PI = 3.14159265358979323846;
        double th0 = PI * ((double)tid + 0.5) / 64.0;
        double th1 = PI * ((double)(tid + 32) + 0.5) / 64.0;
        double ct0 = cos(th0), ct1 = cos(th1);
        double f0 = exp(-z * (ct0 + 1.0));
        double f1 = exp(-z * (ct1 + 1.0));
        double cm2_0 = 1.0, cm1_0 = ct0, tc0 = 2.0 * ct0;
        double cm2_1 = 1.0, cm1_1 = ct1, tc1 = 2.0 * ct1;

        for (int k = 0; k <= MMAX; k++) {
            double ck0, ck1;
            if (k == 0)      { ck0 = 1.0; ck1 = 1.0; }
            else if (k == 1) { ck0 = ct0; ck1 = ct1; }
            else {
                ck0 = tc0 * cm1_0 - cm2_0;  cm2_0 = cm1_0;  cm1_0 = ck0;
                ck1 = tc1 * cm1_1 - cm2_1;  cm2_1 = cm1_1;  cm1_1 = ck1;
            }
            double p = f0 * ck0 + f1 * ck1;
#pragma unroll
            for (int off = 16; off; off >>= 1)
                p += __shfl_xor_sync(0xffffffffu, p, off);
            if (tid == 0) {
                double c = (2.0 / 64.0) * p;
                if (k == 0) c *= 0.5;
                s_c[k] = c;
            }
        }
        __syncwarp();
        if (tid == 0) {
            double tail = 0.0;
            int deg = 2;
            for (int k = MMAX; k >= 2; k--) {
                tail += fabs(s_c[k]);
                if (tail > 3e-5) { deg = k; break; }
            }
            if (deg > MMAX) deg = MMAX;
            s_deg = deg;
            s_a   = (float)(4.0 / lub);
            for (int k = 0; k <= MMAX; k++) s_coef[k] = (float)s_c[k];
        }
    }
    __syncthreads();

    // ============ D) Chebyshev recurrence
    const float d   = s_diag[rl];
    const float a   = s_a;          // 4/lub
    const int   deg = s_deg;        // identical across all blocks
    const int   cnt8 = s_cnt[rl];

    float acc[8], o[8];

    // T1 = (2/lub)*L@x - x ;  out = c0*x + c1*T1
    spmv8(X, ch, s_col[rl], s_val[rl], cnt8, d, yk, acc);
    {
        const float ha = 0.5f * a;
        const float c0 = s_coef[0], c1 = s_coef[1];
#pragma unroll
        for (int i = 0; i < 8; i++) {
            float t1 = ha * acc[i] - yk[i];
            o[i] = c0 * yk[i] + c1 * t1;
            s_ykm1[rl][ch + i] = yk[i];   // T0
            yk[i] = t1;                   // T1
        }
        float4 va = {yk[0], yk[1], yk[2], yk[3]};
        float4 vb = {yk[4], yk[5], yk[6], yk[7]};
        f4_store(g_T1 + ridx, va);
        f4_store(g_T1 + ridx + 4, vb);
    }

    for (int j = 2; j <= deg; j++) {
        flag_barrier(bar_base, bar_num);          // T_{j-1} globally visible
        const float* Tp = (j & 1) ? g_T2 : g_T1;
        float*       Tc = (j & 1) ? g_T1 : g_T2;

        spmv8(Tp, ch, s_col[rl], s_val[rl], cnt8, d, yk, acc);

        const float c = s_coef[j];
        float tn[8];
#pragma unroll
        for (int i = 0; i < 8; i++) {
            tn[i] = a * acc[i] - 2.f * yk[i] - s_ykm1[rl][ch + i];
            o[i] += c * tn[i];
            s_ykm1[rl][ch + i] = yk[i];
            yk[i] = tn[i];
        }
        if (j < deg) {                            // last T never gathered
            float4 va = {tn[0], tn[1], tn[2], tn[3]};
            float4 vb = {tn[4], tn[5], tn[6], tn[7]};
            f4_store(Tc + ridx, va);
            f4_store(Tc + ridx + 4, vb);
        }
    }

    float4 oa = {o[0], o[1], o[2], o[3]};
    float4 ob = {o[4], o[5], o[6], o[7]};
    f4_store(out + ridx, oa);
    f4_store(out + ridx + 4, ob);
}

// ---------------------------------------------------------------------------
extern "C" void kernel_launch(void* const* d_in, const int* in_sizes, int n_in,
                              void* d_out, int out_size) {
    const float* x = nullptr;
    const float* L = nullptr;
    const float* t = nullptr;
    for (int i = 0; i < n_in; i++) {
        if      (in_sizes[i] == NN * DD) x = (const float*)d_in[i];
        else if (in_sizes[i] == NN * NN) L = (const float*)d_in[i];
        else if (in_sizes[i] == 1)       t = (const float*)d_in[i];
    }
    float* out = (float*)d_out;

    cheb_all<<<GRID, THREADS>>>(x, L, t, out);
}

// round 8
// speedup vs baseline: 1.4056x; 1.4056x over previous
#include <cuda_runtime.h>
#include <math.h>

// Diffusion: out = expm(-max(t,1e-8)*L) @ x, L = graph Laplacian (~32 nnz/row).
// Chebyshev expansion of e^{-t*lambda} on [0, lambda_ub] via fp32 sparse
// matvecs, fully fused into ONE persistent kernel:
//   - per-block ELL extraction of its 8 rows from dense L (smem-resident)
//   - certified spectral bound: min(Gershgorin 2*d_max, Merris max(d_u+m_u),
//     Anderson-Morley max edge (d_u+d_v)) -> smaller z -> fewer iterations
//   - redundant per-block fp64 DCT for coefficients (identical across blocks)
//   - R4-proven grid barrier: central atomic counter, ONE poller per block
//     with __nanosleep backoff (flag-array polling regressed in R6)

#define NN   2048
#define DD   512
#define ELLW 128
#define MMAX 48
#define RPB  8            // rows per block
#define TPR  64           // threads per row (8 channels each)
#define THREADS (RPB*TPR) // 512
#define GRID (NN/RPB)     // 256 blocks (<= 148 SMs * 2 resident -> one wave)

// -------- device-global scratch (no allocations allowed) --------
__device__ float g_T1[NN * DD];
__device__ float g_T2[NN * DD];
__device__ float g_degv[NN];        // weighted degree per node
__device__ float g_bmax[GRID];      // per-block max degree
__device__ float g_bmer[GRID];      // per-block max Merris  d_u + m_u
__device__ float g_bam [GRID];      // per-block max edge    d_u + d_vmax

// R4-proven barrier state (self-resetting, replay-safe)
__device__ int          g_bar_count = 0;
__device__ volatile int g_bar_gen   = 0;

__device__ __forceinline__ float4 f4_load(const float* p) {
    return *reinterpret_cast<const float4*>(p);
}
__device__ __forceinline__ void f4_store(float* p, float4 v) {
    *reinterpret_cast<float4*>(p) = v;
}

__device__ __forceinline__ void grid_barrier() {
    __threadfence();
    __syncthreads();
    if (threadIdx.x == 0) {
        int gen = g_bar_gen;
        if (atomicAdd(&g_bar_count, 1) == GRID - 1) {
            g_bar_count = 0;
            __threadfence();
            g_bar_gen = gen + 1;
        } else {
            while (g_bar_gen == gen) __nanosleep(64);
        }
        __threadfence();
    }
    __syncthreads();
}

// ---------------------------------------------------------------------------
// SpMV core: acc[0..7] = d*yk - sum_j val_j * Y[col_j, ch..ch+7]
// ---------------------------------------------------------------------------
__device__ __forceinline__ void spmv8(const float* __restrict__ Y, int ch,
                                      const int* __restrict__ sc,
                                      const float* __restrict__ sv,
                                      int cnt, float d,
                                      const float yk[8], float acc[8]) {
#pragma unroll
    for (int i = 0; i < 8; i++) acc[i] = d * yk[i];
    int k = 0;
    for (; k + 2 <= cnt; k += 2) {
        int   c0 = sc[k],     c1 = sc[k + 1];
        float v0 = sv[k],     v1 = sv[k + 1];
        const float* p0 = Y + (((size_t)c0) << 9) + ch;
        const float* p1 = Y + (((size_t)c1) << 9) + ch;
        float4 a0 = f4_load(p0), a1 = f4_load(p0 + 4);
        float4 b0 = f4_load(p1), b1 = f4_load(p1 + 4);
        acc[0] -= v0 * a0.x; acc[1] -= v0 * a0.y; acc[2] -= v0 * a0.z; acc[3] -= v0 * a0.w;
        acc[4] -= v0 * a1.x; acc[5] -= v0 * a1.y; acc[6] -= v0 * a1.z; acc[7] -= v0 * a1.w;
        acc[0] -= v1 * b0.x; acc[1] -= v1 * b0.y; acc[2] -= v1 * b0.z; acc[3] -= v1 * b0.w;
        acc[4] -= v1 * b1.x; acc[5] -= v1 * b1.y; acc[6] -= v1 * b1.z; acc[7] -= v1 * b1.w;
    }
    if (k < cnt) {
        int   c0 = sc[k];
        float v0 = sv[k];
        const float* p0 = Y + (((size_t)c0) << 9) + ch;
        float4 a0 = f4_load(p0), a1 = f4_load(p0 + 4);
        acc[0] -= v0 * a0.x; acc[1] -= v0 * a0.y; acc[2] -= v0 * a0.z; acc[3] -= v0 * a0.w;
        acc[4] -= v0 * a1.x; acc[5] -= v0 * a1.y; acc[6] -= v0 * a1.z; acc[7] -= v0 * a1.w;
    }
}

// ---------------------------------------------------------------------------
__global__ void __launch_bounds__(THREADS, 2)
cheb_all(const float* __restrict__ X, const float* __restrict__ L,
         const float* __restrict__ t_in, float* __restrict__ out) {
    const int tid  = threadIdx.x;
    const int rl   = tid >> 6;          // row within block (0..7)
    const int lane = tid & 63;          // thread within row (2 warps)
    const int row  = blockIdx.x * RPB + rl;

    __shared__ int    s_col[RPB][ELLW];
    __shared__ float  s_val[RPB][ELLW];
    __shared__ float  s_ykm1[RPB][TPR * 8];
    __shared__ float  s_diag[RPB];
    __shared__ int    s_cnt[RPB];
    __shared__ int    s_wt[RPB][2];
    __shared__ float  s_red[RPB][4];    // cross-warp reduce scratch
    __shared__ float  s_coef[MMAX + 1];
    __shared__ float  s_a;
    __shared__ int    s_deg;
    __shared__ double s_c[MMAX + 1];

    // ============ A) extract this block's 8 rows of dense L into smem ELL
    const float4* Lr4 = reinterpret_cast<const float4*>(L + (size_t)row * NN) + lane * 8;
    int   cnt = 0;
    float dv  = 0.f;
#pragma unroll
    for (int k = 0; k < 8; k++) {
        float4 v = Lr4[k];
        int c = lane * 32 + k * 4;
        if (c + 0 == row) dv = v.x; else cnt += (v.x != 0.f);
        if (c + 1 == row) dv = v.y; else cnt += (v.y != 0.f);
        if (c + 2 == row) dv = v.z; else cnt += (v.z != 0.f);
        if (c + 3 == row) dv = v.w; else cnt += (v.w != 0.f);
    }
    int inc = cnt;
#pragma unroll
    for (int off = 1; off < 32; off <<= 1) {
        int n = __shfl_up_sync(0xffffffffu, inc, off);
        if ((lane & 31) >= off) inc += n;
    }
    const int wir = lane >> 5;
    if ((lane & 31) == 31) s_wt[rl][wir] = inc;
    __syncthreads();
    int offset = inc - cnt + (wir ? s_wt[rl][0] : 0);
    int total  = s_wt[rl][0] + s_wt[rl][1];

    {   // pass 2: re-read (L1-hot) and compact into smem
        int o = offset;
#pragma unroll
        for (int k = 0; k < 8; k++) {
            float4 v = Lr4[k];
            int c = lane * 32 + k * 4;
            if (v.x != 0.f && c + 0 != row && o < ELLW) { s_col[rl][o] = c + 0; s_val[rl][o] = -v.x; o++; }
            if (v.y != 0.f && c + 1 != row && o < ELLW) { s_col[rl][o] = c + 1; s_val[rl][o] = -v.y; o++; }
            if (v.z != 0.f && c + 2 != row && o < ELLW) { s_col[rl][o] = c + 2; s_val[rl][o] = -v.z; o++; }
            if (v.w != 0.f && c + 3 != row && o < ELLW) { s_col[rl][o] = c + 3; s_val[rl][o] = -v.w; o++; }
        }
    }
    if (lane == (row >> 5)) s_diag[rl] = dv;    // owner of diagonal column
    if (lane == 0) s_cnt[rl] = (total < ELLW) ? total : ELLW;
    __syncthreads();

    // publish degree vector + per-block max degree
    if (lane == 0) g_degv[row] = s_diag[rl];
    if (tid == 0) {
        float m = s_diag[0];
#pragma unroll
        for (int i = 1; i < RPB; i++) m = fmaxf(m, s_diag[i]);
        g_bmax[blockIdx.x] = m;
    }

    // issue own-row X loads early
    const int   ch   = lane << 3;
    const size_t ridx = (((size_t)row) << 9) + ch;
    float yk[8];
    {
        float4 xa = f4_load(X + ridx), xb = f4_load(X + ridx + 4);
        yk[0] = xa.x; yk[1] = xa.y; yk[2] = xa.z; yk[3] = xa.w;
        yk[4] = xb.x; yk[5] = xb.y; yk[6] = xb.z; yk[7] = xb.w;
    }

    // ============ B) barrier 1: degree vector visible -> certified bounds
    grid_barrier();
    {
        const int rc = s_cnt[rl];
        float wsum = 0.f, dnbmax = 0.f;
        for (int k = lane; k < rc; k += TPR) {          // at most 1 iter (rc<64)
            float dn = g_degv[s_col[rl][k]];
            wsum  += s_val[rl][k] * dn;
            dnbmax = fmaxf(dnbmax, dn);
        }
#pragma unroll
        for (int off = 16; off; off >>= 1) {
            wsum  += __shfl_xor_sync(0xffffffffu, wsum, off);
            dnbmax = fmaxf(dnbmax, __shfl_xor_sync(0xffffffffu, dnbmax, off));
        }
        if ((lane & 31) == 0) {
            s_red[rl][wir]     = wsum;
            s_red[rl][2 + wir] = dnbmax;
        }
        __syncthreads();
        if (tid == 0) {
            float bm = 0.f, ba = 0.f;
#pragma unroll
            for (int i = 0; i < RPB; i++) {
                float du = s_diag[i];
                float ws = s_red[i][0] + s_red[i][1];
                float nm = fmaxf(s_red[i][2], s_red[i][3]);
                if (du > 1e-20f) bm = fmaxf(bm, du + ws / du);   // Merris
                ba = fmaxf(ba, du + nm);                          // Anderson-Morley
            }
            g_bmer[blockIdx.x] = bm;
            g_bam [blockIdx.x] = ba;
        }
    }

    // ============ C) barrier 2: bounds visible -> coefficients (warp 0, all blocks)
    grid_barrier();
    if (tid < 32) {
        float dm = 0.f, mer = 0.f, am = 0.f;
        for (int i = tid; i < GRID; i += 32) {
            dm  = fmaxf(dm,  g_bmax[i]);
            mer = fmaxf(mer, g_bmer[i]);
            am  = fmaxf(am,  g_bam[i]);
        }
#pragma unroll
        for (int off = 16; off; off >>= 1) {
            dm  = fmaxf(dm,  __shfl_xor_sync(0xffffffffu, dm,  off));
            mer = fmaxf(mer, __shfl_xor_sync(0xffffffffu, mer, off));
            am  = fmaxf(am,  __shfl_xor_sync(0xffffffffu, am,  off));
        }
        double lub = 2.0 * (double)dm;                       // Gershgorin
        double b2  = (double)mer * 1.00001;                  // fp32 guard
        double b3  = (double)am  * 1.00001;
        if (b2 > 1e-12 && b2 < lub) lub = b2;
        if (b3 > 1e-12 && b3 < lub) lub = b3;
        if (lub < 1e-12) lub = 1e-12;

        double tt = (double)fmaxf(t_in[0], 1e-8f);
        double z  = 0.5 * tt * lub;

        const double PI = 3.14159265358979323846;
        double th0 = PI * ((double)tid + 0.5) / 64.0;
        double th1 = PI * ((double)(tid + 32) + 0.5) / 64.0;
        double ct0 = cos(th0), ct1 = cos(th1);
        double f0 = exp(-z * (ct0 + 1.0));
        double f1 = exp(-z * (ct1 + 1.0));
        double cm2_0 = 1.0, cm1_0 = ct0, tc0 = 2.0 * ct0;
        double cm2_1 = 1.0, cm1_1 = ct1, tc1 = 2.0 * ct1;

        for (int k = 0; k <= MMAX; k++) {
            double ck0, ck1;
            if (k == 0)      { ck0 = 1.0; ck1 = 1.0; }
            else if (k == 1) { ck0 = ct0; ck1 = ct1; }
            else {
                ck0 = tc0 * cm1_0 - cm2_0;  cm2_0 = cm1_0;  cm1_0 = ck0;
                ck1 = tc1 * cm1_1 - cm2_1;  cm2_1 = cm1_1;  cm1_1 = ck1;
            }
            double p = f0 * ck0 + f1 * ck1;
#pragma unroll
            for (int off = 16; off; off >>= 1)
                p += __shfl_xor_sync(0xffffffffu, p, off);
            if (tid == 0) {
                double c = (2.0 / 64.0) * p;
                if (k == 0) c *= 0.5;
                s_c[k] = c;
            }
        }
        __syncwarp();
        if (tid == 0) {
            double tail = 0.0;
            int deg = 2;
            for (int k = MMAX; k >= 2; k--) {
                tail += fabs(s_c[k]);
                if (tail > 2e-5) { deg = k; break; }
            }
            if (deg > MMAX) deg = MMAX;
            s_deg = deg;
            s_a   = (float)(4.0 / lub);
            for (int k = 0; k <= MMAX; k++) s_coef[k] = (float)s_c[k];
        }
    }
    __syncthreads();

    // ============ D) Chebyshev recurrence
    const float d    = s_diag[rl];
    const float a    = s_a;          // 4/lub
    const int   deg  = s_deg;        // identical across all blocks
    const int   cnt8 = s_cnt[rl];

    float acc[8], o[8];

    // T1 = (2/lub)*L@x - x ;  out = c0*x + c1*T1
    spmv8(X, ch, s_col[rl], s_val[rl], cnt8, d, yk, acc);
    {
        const float ha = 0.5f * a;
        const float c0 = s_coef[0], c1 = s_coef[1];
#pragma unroll
        for (int i = 0; i < 8; i++) {
            float t1 = ha * acc[i] - yk[i];
            o[i] = c0 * yk[i] + c1 * t1;
            s_ykm1[rl][ch + i] = yk[i];   // T0
            yk[i] = t1;                   // T1
        }
        float4 va = {yk[0], yk[1], yk[2], yk[3]};
        float4 vb = {yk[4], yk[5], yk[6], yk[7]};
        f4_store(g_T1 + ridx, va);
        f4_store(g_T1 + ridx + 4, vb);
    }

    for (int j = 2; j <= deg; j++) {
        grid_barrier();                           // T_{j-1} globally visible
        const float* Tp = (j & 1) ? g_T2 : g_T1;
        float*       Tc = (j & 1) ? g_T1 : g_T2;

        spmv8(Tp, ch, s_col[rl], s_val[rl], cnt8, d, yk, acc);

        const float c = s_coef[j];
        float tn[8];
#pragma unroll
        for (int i = 0; i < 8; i++) {
            tn[i] = a * acc[i] - 2.f * yk[i] - s_ykm1[rl][ch + i];
            o[i] += c * tn[i];
            s_ykm1[rl][ch + i] = yk[i];
            yk[i] = tn[i];
        }
        if (j < deg) {                            // last T never gathered
            float4 va = {tn[0], tn[1], tn[2], tn[3]};
            float4 vb = {tn[4], tn[5], tn[6], tn[7]};
            f4_store(Tc + ridx, va);
            f4_store(Tc + ridx + 4, vb);
        }
    }

    float4 oa = {o[0], o[1], o[2], o[3]};
    float4 ob = {o[4], o[5], o[6], o[7]};
    f4_store(out + ridx, oa);
    f4_store(out + ridx + 4, ob);
}

// ---------------------------------------------------------------------------
extern "C" void kernel_launch(void* const* d_in, const int* in_sizes, int n_in,
                              void* d_out, int out_size) {
    const float* x = nullptr;
    const float* L = nullptr;
    const float* t = nullptr;
    for (int i = 0; i < n_in; i++) {
        if      (in_sizes[i] == NN * DD) x = (const float*)d_in[i];
        else if (in_sizes[i] == NN * NN) L = (const float*)d_in[i];
        else if (in_sizes[i] == 1)       t = (const float*)d_in[i];
    }
    float* out = (float*)d_out;

    cheb_all<<<GRID, THREADS>>>(x, L, t, out);
}

// round 9
// speedup vs baseline: 1.5049x; 1.0707x over previous
#include <cuda_runtime.h>
#include <math.h>

// Diffusion: out = expm(-max(t,1e-8)*L) @ x, L = graph Laplacian (~32 nnz/row).
// Chebyshev expansion of e^{-t*lambda} on [0, lambda_ub], fp32 sparse matvecs,
// ONE persistent kernel. R8 changes (latency-bound fix, ncu: issue 12%, L2 27%):
//   - batch-4 neighbor loop: 8 independent LDG.128 in flight (MLP 4 -> 8)
//   - ELL packed int2(col, val) -> single LDS.64 per neighbor
//   - 128 blocks x 1024 threads (16 rows/block): exactly 1 block/SM, removes
//     the 2x SM work skew of 256-block config; barrier half as wide
//   - proven central-atomic barrier w/ nanosleep; Merris/AM/Gershgorin bounds

#define NN   2048
#define DD   512
#define ELLW 96           // max off-diag nnz per row (mean ~32, max ~60)
#define MMAX 48
#define RPB  16           // rows per block
#define TPR  64           // threads per row (8 channels each)
#define THREADS (RPB*TPR) // 1024
#define GRID (NN/RPB)     // 128 blocks -> 1 per SM, zero skew

// -------- device-global scratch (no allocations allowed) --------
__device__ float g_T1[NN * DD];
__device__ float g_T2[NN * DD];
__device__ float g_degv[NN];        // weighted degree per node
__device__ float g_bmax[GRID];      // per-block max degree
__device__ float g_bmer[GRID];      // per-block max Merris  d_u + m_u
__device__ float g_bam [GRID];      // per-block max edge    d_u + d_vmax

__device__ int          g_bar_count = 0;
__device__ volatile int g_bar_gen   = 0;

__device__ __forceinline__ float4 f4_load(const float* p) {
    return *reinterpret_cast<const float4*>(p);
}
__device__ __forceinline__ void f4_store(float* p, float4 v) {
    *reinterpret_cast<float4*>(p) = v;
}

__device__ __forceinline__ void grid_barrier() {
    __threadfence();
    __syncthreads();
    if (threadIdx.x == 0) {
        int gen = g_bar_gen;
        if (atomicAdd(&g_bar_count, 1) == GRID - 1) {
            g_bar_count = 0;
            __threadfence();
            g_bar_gen = gen + 1;
        } else {
            while (g_bar_gen == gen) __nanosleep(64);
        }
        __threadfence();
    }
    __syncthreads();
}

// ---------------------------------------------------------------------------
// SpMV core: acc[0..7] = d*yk - sum_j val_j * Y[col_j, ch..ch+7]
// batch-4: 8 independent LDG.128 issued before consumption -> MLP 8
// ---------------------------------------------------------------------------
__device__ __forceinline__ void spmv8(const float* __restrict__ Y, int ch,
                                      const int2* __restrict__ se,
                                      int cnt, float d,
                                      const float yk[8], float acc[8]) {
#pragma unroll
    for (int i = 0; i < 8; i++) acc[i] = d * yk[i];
    int k = 0;
    for (; k + 4 <= cnt; k += 4) {
        int2 e0 = se[k], e1 = se[k + 1], e2 = se[k + 2], e3 = se[k + 3];
        const float* p0 = Y + (((size_t)e0.x) << 9) + ch;
        const float* p1 = Y + (((size_t)e1.x) << 9) + ch;
        const float* p2 = Y + (((size_t)e2.x) << 9) + ch;
        const float* p3 = Y + (((size_t)e3.x) << 9) + ch;
        float4 a0 = f4_load(p0), a1 = f4_load(p0 + 4);
        float4 b0 = f4_load(p1), b1 = f4_load(p1 + 4);
        float4 c0 = f4_load(p2), c1 = f4_load(p2 + 4);
        float4 g0 = f4_load(p3), g1 = f4_load(p3 + 4);
        float v0 = __int_as_float(e0.y), v1 = __int_as_float(e1.y);
        float v2 = __int_as_float(e2.y), v3 = __int_as_float(e3.y);
        acc[0] -= v0 * a0.x; acc[1] -= v0 * a0.y; acc[2] -= v0 * a0.z; acc[3] -= v0 * a0.w;
        acc[4] -= v0 * a1.x; acc[5] -= v0 * a1.y; acc[6] -= v0 * a1.z; acc[7] -= v0 * a1.w;
        acc[0] -= v1 * b0.x; acc[1] -= v1 * b0.y; acc[2] -= v1 * b0.z; acc[3] -= v1 * b0.w;
        acc[4] -= v1 * b1.x; acc[5] -= v1 * b1.y; acc[6] -= v1 * b1.z; acc[7] -= v1 * b1.w;
        acc[0] -= v2 * c0.x; acc[1] -= v2 * c0.y; acc[2] -= v2 * c0.z; acc[3] -= v2 * c0.w;
        acc[4] -= v2 * c1.x; acc[5] -= v2 * c1.y; acc[6] -= v2 * c1.z; acc[7] -= v2 * c1.w;
        acc[0] -= v3 * g0.x; acc[1] -= v3 * g0.y; acc[2] -= v3 * g0.z; acc[3] -= v3 * g0.w;
        acc[4] -= v3 * g1.x; acc[5] -= v3 * g1.y; acc[6] -= v3 * g1.z; acc[7] -= v3 * g1.w;
    }
    for (; k < cnt; k++) {
        int2 e0 = se[k];
        float v0 = __int_as_float(e0.y);
        const float* p0 = Y + (((size_t)e0.x) << 9) + ch;
        float4 a0 = f4_load(p0), a1 = f4_load(p0 + 4);
        acc[0] -= v0 * a0.x; acc[1] -= v0 * a0.y; acc[2] -= v0 * a0.z; acc[3] -= v0 * a0.w;
        acc[4] -= v0 * a1.x; acc[5] -= v0 * a1.y; acc[6] -= v0 * a1.z; acc[7] -= v0 * a1.w;
    }
}

// ---------------------------------------------------------------------------
__global__ void __launch_bounds__(THREADS, 1)
cheb_all(const float* __restrict__ X, const float* __restrict__ L,
         const float* __restrict__ t_in, float* __restrict__ out) {
    const int tid  = threadIdx.x;
    const int rl   = tid >> 6;          // row within block (0..15)
    const int lane = tid & 63;          // thread within row (2 warps)
    const int row  = blockIdx.x * RPB + rl;

    __shared__ int2   s_ell[RPB][ELLW];           // (col, val bits)
    __shared__ float  s_ykm1[RPB][TPR * 8];
    __shared__ float  s_diag[RPB];
    __shared__ int    s_cnt[RPB];
    __shared__ int    s_wt[RPB][2];
    __shared__ float  s_red[RPB][4];
    __shared__ float  s_coef[MMAX + 1];
    __shared__ float  s_a;
    __shared__ int    s_deg;
    __shared__ double s_c[MMAX + 1];

    // ============ A) extract this block's 16 rows of dense L into smem ELL
    const float4* Lr4 = reinterpret_cast<const float4*>(L + (size_t)row * NN) + lane * 8;
    int   cnt = 0;
    float dv  = 0.f;
#pragma unroll
    for (int k = 0; k < 8; k++) {
        float4 v = Lr4[k];
        int c = lane * 32 + k * 4;
        if (c + 0 == row) dv = v.x; else cnt += (v.x != 0.f);
        if (c + 1 == row) dv = v.y; else cnt += (v.y != 0.f);
        if (c + 2 == row) dv = v.z; else cnt += (v.z != 0.f);
        if (c + 3 == row) dv = v.w; else cnt += (v.w != 0.f);
    }
    int inc = cnt;
#pragma unroll
    for (int off = 1; off < 32; off <<= 1) {
        int n = __shfl_up_sync(0xffffffffu, inc, off);
        if ((lane & 31) >= off) inc += n;
    }
    const int wir = lane >> 5;
    if ((lane & 31) == 31) s_wt[rl][wir] = inc;
    __syncthreads();
    int offset = inc - cnt + (wir ? s_wt[rl][0] : 0);
    int total  = s_wt[rl][0] + s_wt[rl][1];

    {   // pass 2: re-read (L1-hot) and compact into smem
        int o = offset;
#pragma unroll
        for (int k = 0; k < 8; k++) {
            float4 v = Lr4[k];
            int c = lane * 32 + k * 4;
            if (v.x != 0.f && c + 0 != row && o < ELLW) { s_ell[rl][o] = make_int2(c + 0, __float_as_int(-v.x)); o++; }
            if (v.y != 0.f && c + 1 != row && o < ELLW) { s_ell[rl][o] = make_int2(c + 1, __float_as_int(-v.y)); o++; }
            if (v.z != 0.f && c + 2 != row && o < ELLW) { s_ell[rl][o] = make_int2(c + 2, __float_as_int(-v.z)); o++; }
            if (v.w != 0.f && c + 3 != row && o < ELLW) { s_ell[rl][o] = make_int2(c + 3, __float_as_int(-v.w)); o++; }
        }
    }
    if (lane == (row >> 5)) s_diag[rl] = dv;    // owner of diagonal column
    if (lane == 0) s_cnt[rl] = (total < ELLW) ? total : ELLW;
    __syncthreads();

    if (lane == 0) g_degv[row] = s_diag[rl];
    if (tid == 0) {
        float m = s_diag[0];
#pragma unroll
        for (int i = 1; i < RPB; i++) m = fmaxf(m, s_diag[i]);
        g_bmax[blockIdx.x] = m;
    }

    // own-row X loads early (overlap with barrier + bounds + DCT)
    const int   ch   = lane << 3;
    const size_t ridx = (((size_t)row) << 9) + ch;
    float yk[8];
    {
        float4 xa = f4_load(X + ridx), xb = f4_load(X + ridx + 4);
        yk[0] = xa.x; yk[1] = xa.y; yk[2] = xa.z; yk[3] = xa.w;
        yk[4] = xb.x; yk[5] = xb.y; yk[6] = xb.z; yk[7] = xb.w;
    }

    // ============ B) barrier 1: degree vector visible -> certified bounds
    grid_barrier();
    {
        const int rc = s_cnt[rl];
        float wsum = 0.f, dnbmax = 0.f;
        for (int k = lane; k < rc; k += TPR) {
            int2 e = s_ell[rl][k];
            float dn = g_degv[e.x];
            wsum  += __int_as_float(e.y) * dn;
            dnbmax = fmaxf(dnbmax, dn);
        }
#pragma unroll
        for (int off = 16; off; off >>= 1) {
            wsum  += __shfl_xor_sync(0xffffffffu, wsum, off);
            dnbmax = fmaxf(dnbmax, __shfl_xor_sync(0xffffffffu, dnbmax, off));
        }
        if ((lane & 31) == 0) {
            s_red[rl][wir]     = wsum;
            s_red[rl][2 + wir] = dnbmax;
        }
        __syncthreads();
        if (tid == 0) {
            float bm = 0.f, ba = 0.f;
#pragma unroll
            for (int i = 0; i < RPB; i++) {
                float du = s_diag[i];
                float ws = s_red[i][0] + s_red[i][1];
                float nm = fmaxf(s_red[i][2], s_red[i][3]);
                if (du > 1e-20f) bm = fmaxf(bm, du + ws / du);   // Merris
                ba = fmaxf(ba, du + nm);                          // Anderson-Morley
            }
            g_bmer[blockIdx.x] = bm;
            g_bam [blockIdx.x] = ba;
        }
    }

    // ============ C) barrier 2: bounds visible -> coefficients (warp 0)
    grid_barrier();
    if (tid < 32) {
        float dm = 0.f, mer = 0.f, am = 0.f;
        for (int i = tid; i < GRID; i += 32) {
            dm  = fmaxf(dm,  g_bmax[i]);
            mer = fmaxf(mer, g_bmer[i]);
            am  = fmaxf(am,  g_bam[i]);
        }
#pragma unroll
        for (int off = 16; off; off >>= 1) {
            dm  = fmaxf(dm,  __shfl_xor_sync(0xffffffffu, dm,  off));
            mer = fmaxf(mer, __shfl_xor_sync(0xffffffffu, mer, off));
            am  = fmaxf(am,  __shfl_xor_sync(0xffffffffu, am,  off));
        }
        double lub = 2.0 * (double)dm;                       // Gershgorin
        double b2  = (double)mer * 1.00001;
        double b3  = (double)am  * 1.00001;
        if (b2 > 1e-12 && b2 < lub) lub = b2;
        if (b3 > 1e-12 && b3 < lub) lub = b3;
        if (lub < 1e-12) lub = 1e-12;

        double tt = (double)fmaxf(t_in[0], 1e-8f);
        double z  = 0.5 * tt * lub;

        const double PI = 3.14159265358979323846;
        double th0 = PI * ((double)tid + 0.5) / 64.0;
        double th1 = PI * ((double)(tid + 32) + 0.5) / 64.0;
        double ct0 = cos(th0), ct1 = cos(th1);
        double f0 = exp(-z * (ct0 + 1.0));
        double f1 = exp(-z * (ct1 + 1.0));
        double cm2_0 = 1.0, cm1_0 = ct0, tc0 = 2.0 * ct0;
        double cm2_1 = 1.0, cm1_1 = ct1, tc1 = 2.0 * ct1;

        for (int k = 0; k <= MMAX; k++) {
            double ck0, ck1;
            if (k == 0)      { ck0 = 1.0; ck1 = 1.0; }
            else if (k == 1) { ck0 = ct0; ck1 = ct1; }
            else {
                ck0 = tc0 * cm1_0 - cm2_0;  cm2_0 = cm1_0;  cm1_0 = ck0;
                ck1 = tc1 * cm1_1 - cm2_1;  cm2_1 = cm1_1;  cm1_1 = ck1;
            }
            double p = f0 * ck0 + f1 * ck1;
#pragma unroll
            for (int off = 16; off; off >>= 1)
                p += __shfl_xor_sync(0xffffffffu, p, off);
            if (tid == 0) {
                double c = (2.0 / 64.0) * p;
                if (k == 0) c *= 0.5;
                s_c[k] = c;
            }
        }
        __syncwarp();
        if (tid == 0) {
            double tail = 0.0;
            int deg = 2;
            for (int k = MMAX; k >= 2; k--) {
                tail += fabs(s_c[k]);
                if (tail > 2e-5) { deg = k; break; }
            }
            if (deg > MMAX) deg = MMAX;
            s_deg = deg;
            s_a   = (float)(4.0 / lub);
            for (int k = 0; k <= MMAX; k++) s_coef[k] = (float)s_c[k];
        }
    }
    __syncthreads();

    // ============ D) Chebyshev recurrence
    const float d    = s_diag[rl];
    const float a    = s_a;          // 4/lub
    const int   deg  = s_deg;
    const int   cnt8 = s_cnt[rl];

    float acc[8], o[8];

    // T1 = (2/lub)*L@x - x ;  out = c0*x + c1*T1
    spmv8(X, ch, s_ell[rl], cnt8, d, yk, acc);
    {
        const float ha = 0.5f * a;
        const float c0 = s_coef[0], c1 = s_coef[1];
#pragma unroll
        for (int i = 0; i < 8; i++) {
            float t1 = ha * acc[i] - yk[i];
            o[i] = c0 * yk[i] + c1 * t1;
            s_ykm1[rl][ch + i] = yk[i];   // T0
            yk[i] = t1;                   // T1
        }
        float4 va = {yk[0], yk[1], yk[2], yk[3]};
        float4 vb = {yk[4], yk[5], yk[6], yk[7]};
        f4_store(g_T1 + ridx, va);
        f4_store(g_T1 + ridx + 4, vb);
    }

    for (int j = 2; j <= deg; j++) {
        grid_barrier();                           // T_{j-1} globally visible
        const float* Tp = (j & 1) ? g_T2 : g_T1;
        float*       Tc = (j & 1) ? g_T1 : g_T2;

        spmv8(Tp, ch, s_ell[rl], cnt8, d, yk, acc);

        const float c = s_coef[j];
        float tn[8];
#pragma unroll
        for (int i = 0; i < 8; i++) {
            tn[i] = a * acc[i] - 2.f * yk[i] - s_ykm1[rl][ch + i];
            o[i] += c * tn[i];
            s_ykm1[rl][ch + i] = yk[i];
            yk[i] = tn[i];
        }
        if (j < deg) {                            // last T never gathered
            float4 va = {tn[0], tn[1], tn[2], tn[3]};
            float4 vb = {tn[4], tn[5], tn[6], tn[7]};
            f4_store(Tc + ridx, va);
            f4_store(Tc + ridx + 4, vb);
        }
    }

    float4 oa = {o[0], o[1], o[2], o[3]};
    float4 ob = {o[4], o[5], o[6], o[7]};
    f4_store(out + ridx, oa);
    f4_store(out + ridx + 4, ob);
}

// ---------------------------------------------------------------------------
extern "C" void kernel_launch(void* const* d_in, const int* in_sizes, int n_in,
                              void* d_out, int out_size) {
    const float* x = nullptr;
    const float* L = nullptr;
    const float* t = nullptr;
    for (int i = 0; i < n_in; i++) {
        if      (in_sizes[i] == NN * DD) x = (const float*)d_in[i];
        else if (in_sizes[i] == NN * NN) L = (const float*)d_in[i];
        else if (in_sizes[i] == 1)       t = (const float*)d_in[i];
    }
    float* out = (float*)d_out;

    cheb_all<<<GRID, THREADS>>>(x, L, t, out);
}

// round 10
// speedup vs baseline: 2.0280x; 1.3475x over previous
#include <cuda_runtime.h>
#include <math.h>

// Diffusion: out = expm(-max(t,1e-8)*L) @ x, L = graph Laplacian (~32 nnz/row).
// Chebyshev expansion of e^{-t*lambda} on [0, lambda_ub], fp32 sparse matvecs,
// ONE persistent kernel. R9 change: channel mapping made lane-contiguous.
//   Old: thread ch = lane*8       -> 32B lane stride -> 8 wavefronts per LDG.128
//        (half of every 128B line wasted), ~16 wf per neighbor per warp.
//   New: thread owns [ch0,ch0+3] and [ch0+128,ch0+131], ch0 = wr*256 + lane*4
//        -> every LDG/STG.128 is a contiguous 512B warp segment = 4 wavefronts.
//   Halves L1tex wavefronts for all gathers and stores.

#define NN   2048
#define DD   512
#define ELLW 96           // max off-diag nnz per row (mean ~32, max ~60)
#define MMAX 48
#define RPB  16           // rows per block
#define TPR  64           // threads per row (8 channels each)
#define THREADS (RPB*TPR) // 1024
#define GRID (NN/RPB)     // 128 blocks -> 1 per SM

// -------- device-global scratch (no allocations allowed) --------
__device__ float g_T1[NN * DD];
__device__ float g_T2[NN * DD];
__device__ float g_degv[NN];
__device__ float g_bmax[GRID];
__device__ float g_bmer[GRID];
__device__ float g_bam [GRID];

__device__ int          g_bar_count = 0;
__device__ volatile int g_bar_gen   = 0;

__device__ __forceinline__ float4 f4_load(const float* p) {
    return *reinterpret_cast<const float4*>(p);
}
__device__ __forceinline__ void f4_store(float* p, float4 v) {
    *reinterpret_cast<float4*>(p) = v;
}

__device__ __forceinline__ void grid_barrier() {
    __threadfence();
    __syncthreads();
    if (threadIdx.x == 0) {
        int gen = g_bar_gen;
        if (atomicAdd(&g_bar_count, 1) == GRID - 1) {
            g_bar_count = 0;
            __threadfence();
            g_bar_gen = gen + 1;
        } else {
            while (g_bar_gen == gen) __nanosleep(64);
        }
        __threadfence();
    }
    __syncthreads();
}

// ---------------------------------------------------------------------------
// SpMV core over channels {ch0..ch0+3} u {ch0+128..ch0+131}:
// acc[0..7] = d*yk - sum_j val_j * Y[col_j, ...]; batch-4 neighbors,
// 8 independent lane-contiguous LDG.128 in flight.
// ---------------------------------------------------------------------------
__device__ __forceinline__ void spmv8(const float* __restrict__ Y, int ch0,
                                      const int2* __restrict__ se,
                                      int cnt, float d,
                                      const float yk[8], float acc[8]) {
#pragma unroll
    for (int i = 0; i < 8; i++) acc[i] = d * yk[i];
    int k = 0;
    for (; k + 4 <= cnt; k += 4) {
        int2 e0 = se[k], e1 = se[k + 1], e2 = se[k + 2], e3 = se[k + 3];
        const float* p0 = Y + (((size_t)e0.x) << 9) + ch0;
        const float* p1 = Y + (((size_t)e1.x) << 9) + ch0;
        const float* p2 = Y + (((size_t)e2.x) << 9) + ch0;
        const float* p3 = Y + (((size_t)e3.x) << 9) + ch0;
        float4 a0 = f4_load(p0), a1 = f4_load(p0 + 128);
        float4 b0 = f4_load(p1), b1 = f4_load(p1 + 128);
        float4 c0 = f4_load(p2), c1 = f4_load(p2 + 128);
        float4 g0 = f4_load(p3), g1 = f4_load(p3 + 128);
        float v0 = __int_as_float(e0.y), v1 = __int_as_float(e1.y);
        float v2 = __int_as_float(e2.y), v3 = __int_as_float(e3.y);
        acc[0] -= v0 * a0.x; acc[1] -= v0 * a0.y; acc[2] -= v0 * a0.z; acc[3] -= v0 * a0.w;
        acc[4] -= v0 * a1.x; acc[5] -= v0 * a1.y; acc[6] -= v0 * a1.z; acc[7] -= v0 * a1.w;
        acc[0] -= v1 * b0.x; acc[1] -= v1 * b0.y; acc[2] -= v1 * b0.z; acc[3] -= v1 * b0.w;
        acc[4] -= v1 * b1.x; acc[5] -= v1 * b1.y; acc[6] -= v1 * b1.z; acc[7] -= v1 * b1.w;
        acc[0] -= v2 * c0.x; acc[1] -= v2 * c0.y; acc[2] -= v2 * c0.z; acc[3] -= v2 * c0.w;
        acc[4] -= v2 * c1.x; acc[5] -= v2 * c1.y; acc[6] -= v2 * c1.z; acc[7] -= v2 * c1.w;
        acc[0] -= v3 * g0.x; acc[1] -= v3 * g0.y; acc[2] -= v3 * g0.z; acc[3] -= v3 * g0.w;
        acc[4] -= v3 * g1.x; acc[5] -= v3 * g1.y; acc[6] -= v3 * g1.z; acc[7] -= v3 * g1.w;
    }
    for (; k < cnt; k++) {
        int2 e0 = se[k];
        float v0 = __int_as_float(e0.y);
        const float* p0 = Y + (((size_t)e0.x) << 9) + ch0;
        float4 a0 = f4_load(p0), a1 = f4_load(p0 + 128);
        acc[0] -= v0 * a0.x; acc[1] -= v0 * a0.y; acc[2] -= v0 * a0.z; acc[3] -= v0 * a0.w;
        acc[4] -= v0 * a1.x; acc[5] -= v0 * a1.y; acc[6] -= v0 * a1.z; acc[7] -= v0 * a1.w;
    }
}

// ---------------------------------------------------------------------------
__global__ void __launch_bounds__(THREADS, 1)
cheb_all(const float* __restrict__ X, const float* __restrict__ L,
         const float* __restrict__ t_in, float* __restrict__ out) {
    const int tid  = threadIdx.x;
    const int rl   = tid >> 6;          // row within block (0..15)
    const int lane = tid & 63;          // thread within row (2 warps)
    const int row  = blockIdx.x * RPB + rl;
    const int wir  = lane >> 5;         // warp within row (0/1)

    __shared__ int2   s_ell[RPB][ELLW];
    __shared__ float  s_ykm1[RPB][DD];
    __shared__ float  s_diag[RPB];
    __shared__ int    s_cnt[RPB];
    __shared__ int    s_wt[RPB][2];
    __shared__ float  s_red[RPB][4];
    __shared__ float  s_coef[MMAX + 1];
    __shared__ float  s_a;
    __shared__ int    s_deg;
    __shared__ double s_c[MMAX + 1];

    // ============ A) extract this block's 16 rows of dense L into smem ELL
    const float4* Lr4 = reinterpret_cast<const float4*>(L + (size_t)row * NN) + lane * 8;
    int   cnt = 0;
    float dv  = 0.f;
#pragma unroll
    for (int k = 0; k < 8; k++) {
        float4 v = Lr4[k];
        int c = lane * 32 + k * 4;
        if (c + 0 == row) dv = v.x; else cnt += (v.x != 0.f);
        if (c + 1 == row) dv = v.y; else cnt += (v.y != 0.f);
        if (c + 2 == row) dv = v.z; else cnt += (v.z != 0.f);
        if (c + 3 == row) dv = v.w; else cnt += (v.w != 0.f);
    }
    int inc = cnt;
#pragma unroll
    for (int off = 1; off < 32; off <<= 1) {
        int n = __shfl_up_sync(0xffffffffu, inc, off);
        if ((lane & 31) >= off) inc += n;
    }
    if ((lane & 31) == 31) s_wt[rl][wir] = inc;
    __syncthreads();
    int offset = inc - cnt + (wir ? s_wt[rl][0] : 0);
    int total  = s_wt[rl][0] + s_wt[rl][1];

    {   // pass 2: re-read (L1-hot) and compact into smem
        int o = offset;
#pragma unroll
        for (int k = 0; k < 8; k++) {
            float4 v = Lr4[k];
            int c = lane * 32 + k * 4;
            if (v.x != 0.f && c + 0 != row && o < ELLW) { s_ell[rl][o] = make_int2(c + 0, __float_as_int(-v.x)); o++; }
            if (v.y != 0.f && c + 1 != row && o < ELLW) { s_ell[rl][o] = make_int2(c + 1, __float_as_int(-v.y)); o++; }
            if (v.z != 0.f && c + 2 != row && o < ELLW) { s_ell[rl][o] = make_int2(c + 2, __float_as_int(-v.z)); o++; }
            if (v.w != 0.f && c + 3 != row && o < ELLW) { s_ell[rl][o] = make_int2(c + 3, __float_as_int(-v.w)); o++; }
        }
    }
    if (lane == (row >> 5)) s_diag[rl] = dv;
    if (lane == 0) s_cnt[rl] = (total < ELLW) ? total : ELLW;
    __syncthreads();

    if (lane == 0) g_degv[row] = s_diag[rl];
    if (tid == 0) {
        float m = s_diag[0];
#pragma unroll
        for (int i = 1; i < RPB; i++) m = fmaxf(m, s_diag[i]);
        g_bmax[blockIdx.x] = m;
    }

    // lane-contiguous channel layout: [ch0, ch0+3] and [ch0+128, ch0+131]
    const int   ch0   = wir * 256 + (lane & 31) * 4;
    const size_t ridx0 = (((size_t)row) << 9) + ch0;
    const size_t ridx1 = ridx0 + 128;

    float yk[8];
    {
        float4 xa = f4_load(X + ridx0), xb = f4_load(X + ridx1);
        yk[0] = xa.x; yk[1] = xa.y; yk[2] = xa.z; yk[3] = xa.w;
        yk[4] = xb.x; yk[5] = xb.y; yk[6] = xb.z; yk[7] = xb.w;
    }

    // ============ B) barrier 1: degree vector visible -> certified bounds
    grid_barrier();
    {
        const int rc = s_cnt[rl];
        float wsum = 0.f, dnbmax = 0.f;
        for (int k = lane; k < rc; k += TPR) {
            int2 e = s_ell[rl][k];
            float dn = g_degv[e.x];
            wsum  += __int_as_float(e.y) * dn;
            dnbmax = fmaxf(dnbmax, dn);
        }
#pragma unroll
        for (int off = 16; off; off >>= 1) {
            wsum  += __shfl_xor_sync(0xffffffffu, wsum, off);
            dnbmax = fmaxf(dnbmax, __shfl_xor_sync(0xffffffffu, dnbmax, off));
        }
        if ((lane & 31) == 0) {
            s_red[rl][wir]     = wsum;
            s_red[rl][2 + wir] = dnbmax;
        }
        __syncthreads();
        if (tid == 0) {
            float bm = 0.f, ba = 0.f;
#pragma unroll
            for (int i = 0; i < RPB; i++) {
                float du = s_diag[i];
                float ws = s_red[i][0] + s_red[i][1];
                float nm = fmaxf(s_red[i][2], s_red[i][3]);
                if (du > 1e-20f) bm = fmaxf(bm, du + ws / du);   // Merris
                ba = fmaxf(ba, du + nm);                          // Anderson-Morley
            }
            g_bmer[blockIdx.x] = bm;
            g_bam [blockIdx.x] = ba;
        }
    }

    // ============ C) barrier 2: bounds visible -> coefficients (warp 0)
    grid_barrier();
    if (tid < 32) {
        float dm = 0.f, mer = 0.f, am = 0.f;
        for (int i = tid; i < GRID; i += 32) {
            dm  = fmaxf(dm,  g_bmax[i]);
            mer = fmaxf(mer, g_bmer[i]);
            am  = fmaxf(am,  g_bam[i]);
        }
#pragma unroll
        for (int off = 16; off; off >>= 1) {
            dm  = fmaxf(dm,  __shfl_xor_sync(0xffffffffu, dm,  off));
            mer = fmaxf(mer, __shfl_xor_sync(0xffffffffu, mer, off));
            am  = fmaxf(am,  __shfl_xor_sync(0xffffffffu, am,  off));
        }
        double lub = 2.0 * (double)dm;                       // Gershgorin
        double b2  = (double)mer * 1.00001;
        double b3  = (double)am  * 1.00001;
        if (b2 > 1e-12 && b2 < lub) lub = b2;
        if (b3 > 1e-12 && b3 < lub) lub = b3;
        if (lub < 1e-12) lub = 1e-12;

        double tt = (double)fmaxf(t_in[0], 1e-8f);
        double z  = 0.5 * tt * lub;

        const double PI = 3.14159265358979323846;
        double th0 = PI * ((double)tid + 0.5) / 64.0;
        double th1 = PI * ((double)(tid + 32) + 0.5) / 64.0;
        double ct0 = cos(th0), ct1 = cos(th1);
        double f0 = exp(-z * (ct0 + 1.0));
        double f1 = exp(-z * (ct1 + 1.0));
        double cm2_0 = 1.0, cm1_0 = ct0, tc0 = 2.0 * ct0;
        double cm2_1 = 1.0, cm1_1 = ct1, tc1 = 2.0 * ct1;

        for (int k = 0; k <= MMAX; k++) {
            double ck0, ck1;
            if (k == 0)      { ck0 = 1.0; ck1 = 1.0; }
            else if (k == 1) { ck0 = ct0; ck1 = ct1; }
            else {
                ck0 = tc0 * cm1_0 - cm2_0;  cm2_0 = cm1_0;  cm1_0 = ck0;
                ck1 = tc1 * cm1_1 - cm2_1;  cm2_1 = cm1_1;  cm1_1 = ck1;
            }
            double p = f0 * ck0 + f1 * ck1;
#pragma unroll
            for (int off = 16; off; off >>= 1)
                p += __shfl_xor_sync(0xffffffffu, p, off);
            if (tid == 0) {
                double c = (2.0 / 64.0) * p;
                if (k == 0) c *= 0.5;
                s_c[k] = c;
            }
        }
        __syncwarp();
        if (tid == 0) {
            double tail = 0.0;
            int deg = 2;
            for (int k = MMAX; k >= 2; k--) {
                tail += fabs(s_c[k]);
                if (tail > 2e-5) { deg = k; break; }
            }
            if (deg > MMAX) deg = MMAX;
            s_deg = deg;
            s_a   = (float)(4.0 / lub);
            for (int k = 0; k <= MMAX; k++) s_coef[k] = (float)s_c[k];
        }
    }
    __syncthreads();

    // ============ D) Chebyshev recurrence
    const float d    = s_diag[rl];
    const float a    = s_a;          // 4/lub
    const int   deg  = s_deg;
    const int   cnt8 = s_cnt[rl];

    float acc[8], o[8];

    // T1 = (2/lub)*L@x - x ;  out = c0*x + c1*T1
    spmv8(X, ch0, s_ell[rl], cnt8, d, yk, acc);
    {
        const float ha = 0.5f * a;
        const float c0 = s_coef[0], c1 = s_coef[1];
#pragma unroll
        for (int i = 0; i < 8; i++) {
            float t1 = ha * acc[i] - yk[i];
            o[i] = c0 * yk[i] + c1 * t1;
            int c = ch0 + ((i < 4) ? i : (124 + i));  // i>=4 -> ch0+128+(i-4)
            s_ykm1[rl][c] = yk[i];    // T0
            yk[i] = t1;               // T1
        }
        float4 va = {yk[0], yk[1], yk[2], yk[3]};
        float4 vb = {yk[4], yk[5], yk[6], yk[7]};
        f4_store(g_T1 + ridx0, va);
        f4_store(g_T1 + ridx1, vb);
    }

    for (int j = 2; j <= deg; j++) {
        grid_barrier();                           // T_{j-1} globally visible
        const float* Tp = (j & 1) ? g_T2 : g_T1;
        float*       Tc = (j & 1) ? g_T1 : g_T2;

        spmv8(Tp, ch0, s_ell[rl], cnt8, d, yk, acc);

        const float c = s_coef[j];
        float tn[8];
#pragma unroll
        for (int i = 0; i < 8; i++) {
            int cc = ch0 + ((i < 4) ? i : (124 + i));
            tn[i] = a * acc[i] - 2.f * yk[i] - s_ykm1[rl][cc];
            o[i] += c * tn[i];
            s_ykm1[rl][cc] = yk[i];
            yk[i] = tn[i];
        }
        if (j < deg) {                            // last T never gathered
            float4 va = {tn[0], tn[1], tn[2], tn[3]};
            float4 vb = {tn[4], tn[5], tn[6], tn[7]};
            f4_store(Tc + ridx0, va);
            f4_store(Tc + ridx1, vb);
        }
    }

    float4 oa = {o[0], o[1], o[2], o[3]};
    float4 ob = {o[4], o[5], o[6], o[7]};
    f4_store(out + ridx0, oa);
    f4_store(out + ridx1, ob);
}

// ---------------------------------------------------------------------------
extern "C" void kernel_launch(void* const* d_in, const int* in_sizes, int n_in,
                              void* d_out, int out_size) {
    const float* x = nullptr;
    const float* L = nullptr;
    const float* t = nullptr;
    for (int i = 0; i < n_in; i++) {
        if      (in_sizes[i] == NN * DD) x = (const float*)d_in[i];
        else if (in_sizes[i] == NN * NN) L = (const float*)d_in[i];
        else if (in_sizes[i] == 1)       t = (const float*)d_in[i];
    }
    float* out = (float*)d_out;

    cheb_all<<<GRID, THREADS>>>(x, L, t, out);
}